// round 3
// baseline (speedup 1.0000x reference)
#include <cuda_runtime.h>

#define D        256
#define HEADS    8
#define DH       2048     // D*HEADS
#define TM       32       // tokens per CTA
#define NTHREADS 256

#define SQ_PITCH 36       // 144B rows -> 16B aligned for LDS.128 broadcast reads
#define SK_PITCH 33       // odd pitch -> conflict-free strided reads/writes

// shared memory layout (floats)
#define OFF_X   0
#define OFF_Q   (OFF_X + D * TM)                  // 8192
#define OFF_K   (OFF_Q + 256 * SQ_PITCH)          // + 9216
#define OFF_P   (OFF_K + 256 * SK_PITCH)          // + 8448
#define SMEM_FLOATS (OFF_P + TM * HEADS * HEADS)  // + 2048 = 27904 floats = 111616 B

// ---- packed f32x2 helpers (B300: FFMA2 gives 2x fp32 FMA rate vs 3-reg FFMA) ----
__device__ __forceinline__ unsigned long long pack2(float x, float y) {
    unsigned long long r;
    asm("mov.b64 %0, {%1, %2};" : "=l"(r) : "f"(x), "f"(y));
    return r;
}
__device__ __forceinline__ void unpack2(unsigned long long v, float& x, float& y) {
    asm("mov.b64 {%0, %1}, %2;" : "=f"(x), "=f"(y) : "l"(v));
}
__device__ __forceinline__ unsigned long long fma2(unsigned long long a,
                                                   unsigned long long b,
                                                   unsigned long long c) {
    unsigned long long d;
    asm("fma.rn.f32x2 %0, %1, %2, %3;" : "=l"(d) : "l"(a), "l"(b), "l"(c));
    return d;
}

__global__ void __launch_bounds__(NTHREADS, 2)
attn_fused_kernel(const float* __restrict__ x,
                  const float* __restrict__ Wq, const float* __restrict__ bq,
                  const float* __restrict__ Wk, const float* __restrict__ bk,
                  const float* __restrict__ Wv, const float* __restrict__ bv,
                  const float* __restrict__ Wo, const float* __restrict__ bo,
                  float* __restrict__ out)
{
    extern __shared__ float sm[];
    float* sX = sm + OFF_X;   // [k][t]   k*32 + t
    float* sQ = sm + OFF_Q;   // [c][t]   c*36 + t   (reused as sO in phase 3)
    float* sK = sm + OFF_K;   // [c][t]   c*33 + t   (reused as sV in phase 3)
    float* sP = sm + OFF_P;   // [t][h][g]

    const int tid = threadIdx.x;
    const int g0  = blockIdx.x * TM;   // first token of this tile

    // ---------------- phase 0: load X tile ----------------
    {
        const float* xin = x + g0 * D;
        for (int i = tid; i < TM * D; i += NTHREADS) {
            int t = i >> 8;          // i / 256
            int k = i & (D - 1);
            sX[k * TM + t] = xin[i];
        }
    }
    __syncthreads();

    const int head = tid >> 5;   // 0..7   (column-group mapping for GEMMs)
    const int dd   = tid & 31;
    const int lt   = tid >> 3;   // 0..31  (token mapping for logits/softmax)
    const int lh   = tid & 7;    // 0..7

    float accL[HEADS];
    #pragma unroll
    for (int g = 0; g < HEADS; g++) accL[g] = 0.f;

    // ---------------- phase 1: Q/K projection chunks + logit accumulation ----------------
    for (int dc = 0; dc < 8; dc++) {
        const int j = head * D + dc * 32 + dd;   // weight column for this thread
        unsigned long long aq[16], ak[16];
        #pragma unroll
        for (int i = 0; i < 16; i++) { aq[i] = 0ull; ak[i] = 0ull; }
        const float* wqp = Wq + j;
        const float* wkp = Wk + j;
        #pragma unroll 4
        for (int k = 0; k < D; k++) {
            float wqv = wqp[k * DH];
            float wkv = wkp[k * DH];
            unsigned long long wq2 = pack2(wqv, wqv);
            unsigned long long wk2 = pack2(wkv, wkv);
            const ulonglong2* xv = reinterpret_cast<const ulonglong2*>(sX + k * TM);
            #pragma unroll
            for (int tt = 0; tt < 8; tt++) {
                ulonglong2 xp = xv[tt];          // 4 tokens, broadcast LDS.128
                aq[2*tt]   = fma2(xp.x, wq2, aq[2*tt]);
                aq[2*tt+1] = fma2(xp.y, wq2, aq[2*tt+1]);
                ak[2*tt]   = fma2(xp.x, wk2, ak[2*tt]);
                ak[2*tt+1] = fma2(xp.y, wk2, ak[2*tt+1]);
            }
        }
        const float bqv = bq[j];
        const float bkv = bk[j];
        #pragma unroll
        for (int i = 0; i < 16; i++) {
            float f0, f1;
            unpack2(aq[i], f0, f1);
            sQ[tid * SQ_PITCH + 2*i]     = f0 + bqv;
            sQ[tid * SQ_PITCH + 2*i + 1] = f1 + bqv;
            unpack2(ak[i], f0, f1);
            sK[tid * SK_PITCH + 2*i]     = f0 + bkv;
            sK[tid * SK_PITCH + 2*i + 1] = f1 + bkv;
        }
        __syncthreads();
        // logit accumulation: thread owns token lt, query-head lh
        #pragma unroll 4
        for (int d2 = 0; d2 < 32; d2++) {
            float qv = sQ[(lh * 32 + d2) * SQ_PITCH + lt];
            #pragma unroll
            for (int g = 0; g < HEADS; g++)
                accL[g] = fmaf(qv, sK[(g * 32 + d2) * SK_PITCH + lt], accL[g]);
        }
        __syncthreads();
    }

    // ---------------- phase 2: softmax (8-wide, per (token, head) in registers) ----------------
    {
        const float scale = 0.0625f;   // 256^-0.5
        float m = -3.4e38f;
        #pragma unroll
        for (int g = 0; g < HEADS; g++) { accL[g] *= scale; m = fmaxf(m, accL[g]); }
        float s = 0.f;
        #pragma unroll
        for (int g = 0; g < HEADS; g++) { accL[g] = expf(accL[g] - m); s += accL[g]; }
        const float inv = 1.f / s;
        #pragma unroll
        for (int g = 0; g < HEADS; g++)
            sP[(lt * HEADS + lh) * HEADS + g] = accL[g] * inv;
    }
    // visibility of sP is guaranteed by the __syncthreads() inside phase 3 before first read

    // ---------------- phase 3: V chunks -> O chunks -> streamed output GEMM ----------------
    unsigned long long ay[16];
    #pragma unroll
    for (int i = 0; i < 16; i++) ay[i] = 0ull;

    for (int dc = 0; dc < 8; dc++) {
        // (a) V chunk: V[t, g*32+dd] for d-range dc
        const int j = head * D + dc * 32 + dd;
        unsigned long long av[16];
        #pragma unroll
        for (int i = 0; i < 16; i++) av[i] = 0ull;
        const float* wvp = Wv + j;
        #pragma unroll 4
        for (int k = 0; k < D; k++) {
            float wvv = wvp[k * DH];
            unsigned long long wv2 = pack2(wvv, wvv);
            const ulonglong2* xv = reinterpret_cast<const ulonglong2*>(sX + k * TM);
            #pragma unroll
            for (int tt = 0; tt < 8; tt++) {
                ulonglong2 xp = xv[tt];
                av[2*tt]   = fma2(xp.x, wv2, av[2*tt]);
                av[2*tt+1] = fma2(xp.y, wv2, av[2*tt+1]);
            }
        }
        const float bvv = bv[j];
        #pragma unroll
        for (int i = 0; i < 16; i++) {
            float f0, f1;
            unpack2(av[i], f0, f1);
            sK[tid * SK_PITCH + 2*i]     = f0 + bvv;   // sV lives in sK buffer
            sK[tid * SK_PITCH + 2*i + 1] = f1 + bvv;
        }
        __syncthreads();

        // (b) O chunk: O[t, head*32+dd] = sum_g P[t,head,g] * V[t, g*32+dd]
        #pragma unroll 4
        for (int t = 0; t < TM; t++) {
            const float* pp = sP + (t * HEADS + head) * HEADS;   // broadcast across warp
            float o = 0.f;
            #pragma unroll
            for (int g = 0; g < HEADS; g++)
                o = fmaf(pp[g], sK[(g * 32 + dd) * SK_PITCH + t], o);
            sQ[tid * SQ_PITCH + t] = o;    // sO lives in sQ buffer
        }
        __syncthreads();

        // (c) Y accumulation: thread owns output column n = tid
        const int wbase = dc * 32;
        #pragma unroll 4
        for (int c2 = 0; c2 < 256; c2++) {
            const int wr = (c2 >> 5) * D + wbase + (c2 & 31);    // Wo row for O-chunk col c2
            float wo = Wo[wr * D + tid];
            unsigned long long wo2 = pack2(wo, wo);
            const ulonglong2* ov = reinterpret_cast<const ulonglong2*>(sQ + c2 * SQ_PITCH);
            #pragma unroll
            for (int tt = 0; tt < 8; tt++) {
                ulonglong2 op = ov[tt];
                ay[2*tt]   = fma2(op.x, wo2, ay[2*tt]);
                ay[2*tt+1] = fma2(op.y, wo2, ay[2*tt+1]);
            }
        }
        __syncthreads();
    }

    // ---------------- phase 4: bias + coalesced writeout ----------------
    const float bov = bo[tid];
    float yv[TM];
    #pragma unroll
    for (int i = 0; i < 16; i++) unpack2(ay[i], yv[2*i], yv[2*i+1]);
    float* op = out + g0 * D + tid;
    #pragma unroll
    for (int t = 0; t < TM; t++)
        op[t * D] = yv[t] + bov;
}

extern "C" void kernel_launch(void* const* d_in, const int* in_sizes, int n_in,
                              void* d_out, int out_size) {
    const float* x  = (const float*)d_in[0];
    const float* Wq = (const float*)d_in[1];
    const float* bq = (const float*)d_in[2];
    const float* Wk = (const float*)d_in[3];
    const float* bk = (const float*)d_in[4];
    const float* Wv = (const float*)d_in[5];
    const float* bv = (const float*)d_in[6];
    const float* Wo = (const float*)d_in[7];
    const float* bo = (const float*)d_in[8];
    float* out = (float*)d_out;

    const int T = in_sizes[0] / D;          // 16384 tokens
    const int grid = T / TM;                // 512 CTAs
    const size_t smem = SMEM_FLOATS * sizeof(float);

    cudaFuncSetAttribute(attn_fused_kernel,
                         cudaFuncAttributeMaxDynamicSharedMemorySize, (int)smem);
    attn_fused_kernel<<<grid, NTHREADS, smem>>>(x, Wq, bq, Wk, bk, Wv, bv, Wo, bo, out);
}

// round 5
// speedup vs baseline: 1.9049x; 1.9049x over previous
#include <cuda_runtime.h>
#include <cuda_bf16.h>
#include <cstdint>

#define TOK   16384
#define DIN   256
#define DH    2048
#define HEADS 8

// ---------------- device scratch ----------------
__device__ float         g_Q[(size_t)TOK * DH];
__device__ float         g_K[(size_t)TOK * DH];
__device__ float         g_V[(size_t)TOK * DH];
__device__ __nv_bfloat16 g_Xhi[(size_t)TOK * DIN], g_Xlo[(size_t)TOK * DIN];
__device__ __nv_bfloat16 g_Ohi[(size_t)TOK * DH],  g_Olo[(size_t)TOK * DH];
__device__ __nv_bfloat16 g_Wqhi[DH * DIN], g_Wqlo[DH * DIN];   // [n][k]
__device__ __nv_bfloat16 g_Wkhi[DH * DIN], g_Wklo[DH * DIN];
__device__ __nv_bfloat16 g_Wvhi[DH * DIN], g_Wvlo[DH * DIN];
__device__ __nv_bfloat16 g_Wohi[DIN * DH], g_Wolo[DIN * DH];   // Wo^T [n=256][k=2048]

// ---------------- helpers ----------------
__device__ __forceinline__ uint32_t smem_u32(const void* p) {
    uint32_t a;
    asm("{ .reg .u64 t; cvta.to.shared.u64 t, %1; cvt.u32.u64 %0, t; }" : "=r"(a) : "l"(p));
    return a;
}
__device__ __forceinline__ void cpa16(uint32_t dst, const void* src) {
    asm volatile("cp.async.cg.shared.global [%0], [%1], 16;" :: "r"(dst), "l"(src));
}
#define CP_COMMIT() asm volatile("cp.async.commit_group;" ::: "memory")
#define CP_WAIT(n)  asm volatile("cp.async.wait_group %0;" :: "n"(n) : "memory")

#define LDSM4(r, a) asm volatile( \
    "ldmatrix.sync.aligned.m8n8.x4.shared.b16 {%0,%1,%2,%3}, [%4];" \
    : "=r"((r)[0]), "=r"((r)[1]), "=r"((r)[2]), "=r"((r)[3]) : "r"(a))

#define MMA16816(c, a, b0, b1) asm volatile( \
    "mma.sync.aligned.m16n8k16.row.col.f32.bf16.bf16.f32 " \
    "{%0,%1,%2,%3}, {%4,%5,%6,%7}, {%8,%9}, {%0,%1,%2,%3};" \
    : "+f"((c)[0]), "+f"((c)[1]), "+f"((c)[2]), "+f"((c)[3]) \
    : "r"((a)[0]), "r"((a)[1]), "r"((a)[2]), "r"((a)[3]), "r"(b0), "r"(b1))

__device__ __forceinline__ void split_bf(float v, __nv_bfloat16& h, __nv_bfloat16& l) {
    h = __float2bfloat16(v);
    l = __float2bfloat16(v - __bfloat162float(h));
}

// ============================================================================
// X split:  x fp32 [TOK][256] -> g_Xhi/g_Xlo bf16
// ============================================================================
__global__ void xsplit(const float4* __restrict__ x) {
    size_t i = (size_t)blockIdx.x * blockDim.x + threadIdx.x;   // 1M threads, 4 elems each
    float4 f = x[i];
    __nv_bfloat16 h0, l0, h1, l1, h2, l2, h3, l3;
    split_bf(f.x, h0, l0); split_bf(f.y, h1, l1);
    split_bf(f.z, h2, l2); split_bf(f.w, h3, l3);
    __nv_bfloat162* ph = reinterpret_cast<__nv_bfloat162*>(g_Xhi) + 2 * i;
    __nv_bfloat162* pl = reinterpret_cast<__nv_bfloat162*>(g_Xlo) + 2 * i;
    ph[0] = __nv_bfloat162(h0, h1); ph[1] = __nv_bfloat162(h2, h3);
    pl[0] = __nv_bfloat162(l0, l1); pl[1] = __nv_bfloat162(l2, l3);
}

// ============================================================================
// weight transpose + hi/lo split:  W[K][N] -> oh/ol[N][K]
// ============================================================================
__global__ void wconv(const float* __restrict__ W, __nv_bfloat16* __restrict__ oh,
                      __nv_bfloat16* __restrict__ ol, int K, int N) {
    __shared__ float s[64][65];
    int nt = N / 64;
    int n0 = (blockIdx.x % nt) * 64, k0 = (blockIdx.x / nt) * 64;
    int tx = threadIdx.x & 63, ty = threadIdx.x >> 6;
    for (int r = ty; r < 64; r += 4)
        s[r][tx] = W[(size_t)(k0 + r) * N + n0 + tx];
    __syncthreads();
    for (int r = ty; r < 64; r += 4) {
        __nv_bfloat16 h, l;
        split_bf(s[tx][r], h, l);
        size_t o = (size_t)(n0 + r) * K + k0 + tx;
        oh[o] = h; ol[o] = l;
    }
}

// ============================================================================
// generic split-bf16 TN GEMM:  C[M][ldc] = A[M][K] @ B[N][K]^T + bias
// CTA 128x128, 8 warps (2m x 4n), warp tile 64x32, BK=32, double-buffered.
// 3-term split: Ah*Bh + Ah*Bl + Al*Bh
// smem per stage: Ah(10240) Al(10240) Bh(10240) Bl(10240) @ pitch 80B
// ============================================================================
#define GSTAGE 40960
#define GSMEM  (2 * GSTAGE)

__global__ void __launch_bounds__(256, 2)
gemm_bf16(const __nv_bfloat16* __restrict__ Ah, const __nv_bfloat16* __restrict__ Al, int lda,
          const __nv_bfloat16* __restrict__ Bh, const __nv_bfloat16* __restrict__ Bl, int ldb,
          const float* __restrict__ bias, float* __restrict__ C, int ldc, int K)
{
    extern __shared__ char smem[];
    const uint32_t sbase = smem_u32(smem);
    const int tid = threadIdx.x, lane = tid & 31, wid = tid >> 5;
    const int wm = wid >> 2, wn = wid & 3;
    const size_t m0 = (size_t)blockIdx.x * 128;
    const size_t n0 = (size_t)blockIdx.y * 128;

    float acc[4][4][4];
    #pragma unroll
    for (int a = 0; a < 4; a++)
        #pragma unroll
        for (int b = 0; b < 4; b++)
            #pragma unroll
            for (int c = 0; c < 4; c++) acc[a][b][c] = 0.f;

    const int r = tid >> 1;            // 0..127  (row for cp.async: 2 chunks/thread/array)
    const int cc0 = (tid & 1) * 2;     // chunk 0/2

    const int KT = K / 32;

    // stage loader: 128 rows x 4 x 16B chunks per array
    #define LOAD_STAGE(s, kb) do { \
        uint32_t d = sbase + (s) * GSTAGE; \
        const __nv_bfloat16* pah = Ah + (m0 + r) * (size_t)lda + (kb); \
        const __nv_bfloat16* pal = Al + (m0 + r) * (size_t)lda + (kb); \
        const __nv_bfloat16* pbh = Bh + (n0 + r) * (size_t)ldb + (kb); \
        const __nv_bfloat16* pbl = Bl + (n0 + r) * (size_t)ldb + (kb); \
        cpa16(d +         r * 80 + cc0 * 16,        pah + cc0 * 8); \
        cpa16(d +         r * 80 + (cc0 + 1) * 16,  pah + (cc0 + 1) * 8); \
        cpa16(d + 10240 + r * 80 + cc0 * 16,        pal + cc0 * 8); \
        cpa16(d + 10240 + r * 80 + (cc0 + 1) * 16,  pal + (cc0 + 1) * 8); \
        cpa16(d + 20480 + r * 80 + cc0 * 16,        pbh + cc0 * 8); \
        cpa16(d + 20480 + r * 80 + (cc0 + 1) * 16,  pbh + (cc0 + 1) * 8); \
        cpa16(d + 30720 + r * 80 + cc0 * 16,        pbl + cc0 * 8); \
        cpa16(d + 30720 + r * 80 + (cc0 + 1) * 16,  pbl + (cc0 + 1) * 8); \
    } while (0)

    LOAD_STAGE(0, 0);
    CP_COMMIT();

    for (int kt = 0; kt < KT; kt++) {
        if (kt + 1 < KT) {
            LOAD_STAGE((kt + 1) & 1, (kt + 1) * 32);
            CP_COMMIT();
            CP_WAIT(1);
        } else {
            CP_WAIT(0);
        }
        __syncthreads();

        const uint32_t s = sbase + (kt & 1) * GSTAGE;
        const uint32_t arow = s +         (wm * 64 + (lane & 15)) * 80 + (lane >> 4) * 16;
        const uint32_t brow = s + 20480 + (wn * 32 + (lane & 15)) * 80 + (lane >> 4) * 16;

        #pragma unroll
        for (int kh = 0; kh < 2; kh++) {
            uint32_t bh[2][4], bl[2][4];
            #pragma unroll
            for (int ng = 0; ng < 2; ng++) {
                LDSM4(bh[ng], brow + ng * 1280 + kh * 32);
                LDSM4(bl[ng], brow + 10240 + ng * 1280 + kh * 32);
            }
            #pragma unroll
            for (int mf = 0; mf < 4; mf++) {
                uint32_t ah[4], al[4];
                LDSM4(ah, arow + mf * 1280 + kh * 32);
                LDSM4(al, arow + 10240 + mf * 1280 + kh * 32);
                #pragma unroll
                for (int ng = 0; ng < 2; ng++) {
                    #pragma unroll
                    for (int nn = 0; nn < 2; nn++) {
                        float* c = acc[mf][ng * 2 + nn];
                        MMA16816(c, ah, bh[ng][nn], bh[ng][nn + 2]);
                        MMA16816(c, ah, bl[ng][nn], bl[ng][nn + 2]);
                        MMA16816(c, al, bh[ng][nn], bh[ng][nn + 2]);
                    }
                }
            }
        }
        __syncthreads();
    }

    // epilogue: bias + store
    #pragma unroll
    for (int mf = 0; mf < 4; mf++) {
        const size_t row = m0 + wm * 64 + mf * 16 + (lane >> 2);
        #pragma unroll
        for (int nf = 0; nf < 4; nf++) {
            const size_t col = n0 + wn * 32 + nf * 8 + (lane & 3) * 2;
            const float b0 = __ldg(bias + col), b1 = __ldg(bias + col + 1);
            float2 v0 = { acc[mf][nf][0] + b0, acc[mf][nf][1] + b1 };
            float2 v1 = { acc[mf][nf][2] + b0, acc[mf][nf][3] + b1 };
            *reinterpret_cast<float2*>(C + row * (size_t)ldc + col)       = v0;
            *reinterpret_cast<float2*>(C + (row + 8) * (size_t)ldc + col) = v1;
        }
    }
}

// ============================================================================
// attention: per-token 8x8 head-vs-head softmax. 32 tokens/CTA.
// reads g_Q/g_K/g_V fp32, writes g_Ohi/g_Olo bf16
// ============================================================================
#define AP 33
#define ATT_SMEM ((256 * AP * 2 + 2048) * 4)

__global__ void __launch_bounds__(256, 2) attn_kernel() {
    extern __shared__ float sm[];
    float* sQ = sm;
    float* sK = sm + 256 * AP;
    float* sP = sm + 512 * AP;
    const int tid = threadIdx.x;
    const int g0 = blockIdx.x * 32;
    const int lt = tid >> 3, lh = tid & 7;

    float accL[HEADS];
    #pragma unroll
    for (int g = 0; g < HEADS; g++) accL[g] = 0.f;

    for (int dc = 0; dc < 8; dc++) {
        for (int i = tid; i < 8192; i += 256) {
            int t = i >> 8, c = i & 255;
            int j = (c >> 5) * DIN + dc * 32 + (c & 31);
            size_t src = (size_t)(g0 + t) * DH + j;
            sQ[c * AP + t] = g_Q[src];
            sK[c * AP + t] = g_K[src];
        }
        __syncthreads();
        #pragma unroll 4
        for (int d2 = 0; d2 < 32; d2++) {
            float qv = sQ[(lh * 32 + d2) * AP + lt];
            #pragma unroll
            for (int g = 0; g < HEADS; g++)
                accL[g] = fmaf(qv, sK[(g * 32 + d2) * AP + lt], accL[g]);
        }
        __syncthreads();
    }
    {
        const float scale = 0.0625f;
        float m = -3.4e38f;
        #pragma unroll
        for (int g = 0; g < HEADS; g++) { accL[g] *= scale; m = fmaxf(m, accL[g]); }
        float s = 0.f;
        #pragma unroll
        for (int g = 0; g < HEADS; g++) { accL[g] = __expf(accL[g] - m); s += accL[g]; }
        float inv = 1.f / s;
        #pragma unroll
        for (int g = 0; g < HEADS; g++)
            sP[(lt * HEADS + lh) * HEADS + g] = accL[g] * inv;
    }
    const int head = tid >> 5, dd = tid & 31;
    for (int dc = 0; dc < 8; dc++) {
        for (int i = tid; i < 8192; i += 256) {
            int t = i >> 8, c = i & 255;
            int j = (c >> 5) * DIN + dc * 32 + (c & 31);
            sK[c * AP + t] = g_V[(size_t)(g0 + t) * DH + j];
        }
        __syncthreads();   // also publishes sP on dc=0
        const int j = head * DIN + dc * 32 + dd;
        #pragma unroll 4
        for (int t = 0; t < 32; t++) {
            const float* pp = sP + (t * HEADS + head) * HEADS;
            float o = 0.f;
            #pragma unroll
            for (int g = 0; g < HEADS; g++)
                o = fmaf(pp[g], sK[(g * 32 + dd) * AP + t], o);
            __nv_bfloat16 h, l;
            split_bf(o, h, l);
            size_t dst = (size_t)(g0 + t) * DH + j;
            g_Ohi[dst] = h;
            g_Olo[dst] = l;
        }
        __syncthreads();
    }
}

// ============================================================================
extern "C" void kernel_launch(void* const* d_in, const int* in_sizes, int n_in,
                              void* d_out, int out_size) {
    const float* x  = (const float*)d_in[0];
    const float* Wq = (const float*)d_in[1];
    const float* bq = (const float*)d_in[2];
    const float* Wk = (const float*)d_in[3];
    const float* bk = (const float*)d_in[4];
    const float* Wv = (const float*)d_in[5];
    const float* bv = (const float*)d_in[6];
    const float* Wo = (const float*)d_in[7];
    const float* bo = (const float*)d_in[8];
    float* out = (float*)d_out;

    cudaFuncSetAttribute(gemm_bf16,   cudaFuncAttributeMaxDynamicSharedMemorySize, GSMEM);
    cudaFuncSetAttribute(attn_kernel, cudaFuncAttributeMaxDynamicSharedMemorySize, ATT_SMEM);

    // device-symbol addresses (host side)
    __nv_bfloat16 *Xhi, *Xlo, *Ohi, *Olo;
    __nv_bfloat16 *Wqh, *Wql, *Wkh, *Wkl, *Wvh, *Wvl, *Woh, *Wol;
    float *Qp, *Kp, *Vp;
    cudaGetSymbolAddress((void**)&Xhi, g_Xhi);  cudaGetSymbolAddress((void**)&Xlo, g_Xlo);
    cudaGetSymbolAddress((void**)&Ohi, g_Ohi);  cudaGetSymbolAddress((void**)&Olo, g_Olo);
    cudaGetSymbolAddress((void**)&Wqh, g_Wqhi); cudaGetSymbolAddress((void**)&Wql, g_Wqlo);
    cudaGetSymbolAddress((void**)&Wkh, g_Wkhi); cudaGetSymbolAddress((void**)&Wkl, g_Wklo);
    cudaGetSymbolAddress((void**)&Wvh, g_Wvhi); cudaGetSymbolAddress((void**)&Wvl, g_Wvlo);
    cudaGetSymbolAddress((void**)&Woh, g_Wohi); cudaGetSymbolAddress((void**)&Wol, g_Wolo);
    cudaGetSymbolAddress((void**)&Qp, g_Q);
    cudaGetSymbolAddress((void**)&Kp, g_K);
    cudaGetSymbolAddress((void**)&Vp, g_V);

    // prep
    xsplit<<<4096, 256>>>((const float4*)x);
    wconv<<<128, 256>>>(Wq, Wqh, Wql, DIN, DH);
    wconv<<<128, 256>>>(Wk, Wkh, Wkl, DIN, DH);
    wconv<<<128, 256>>>(Wv, Wvh, Wvl, DIN, DH);
    wconv<<<128, 256>>>(Wo, Woh, Wol, DH, DIN);

    // QKV projections: M=16384, N=2048, K=256
    dim3 g1(TOK / 128, DH / 128);
    gemm_bf16<<<g1, 256, GSMEM>>>(Xhi, Xlo, DIN, Wqh, Wql, DIN, bq, Qp, DH, DIN);
    gemm_bf16<<<g1, 256, GSMEM>>>(Xhi, Xlo, DIN, Wkh, Wkl, DIN, bk, Kp, DH, DIN);
    gemm_bf16<<<g1, 256, GSMEM>>>(Xhi, Xlo, DIN, Wvh, Wvl, DIN, bv, Vp, DH, DIN);

    // attention
    attn_kernel<<<TOK / 32, 256, ATT_SMEM>>>();

    // out-proj: M=16384, N=256, K=2048
    dim3 g2(TOK / 128, DIN / 128);
    gemm_bf16<<<g2, 256, GSMEM>>>(Ohi, Olo, DH, Woh, Wol, DH, bo, out, DIN, DH);
}

// round 6
// speedup vs baseline: 2.4635x; 1.2932x over previous
#include <cuda_runtime.h>
#include <cuda_fp16.h>
#include <cstdint>

#define TOK   16384
#define DIN   256
#define DH    2048
#define HEADS 8

// ---------------- device scratch ----------------
__device__ float  g_Q[(size_t)TOK * DH];
__device__ float  g_K[(size_t)TOK * DH];
__device__ float  g_V[(size_t)TOK * DH];
__device__ __half g_Xhi[(size_t)TOK * DIN], g_Xlo[(size_t)TOK * DIN];
__device__ __half g_Ohi[(size_t)TOK * DH],  g_Olo[(size_t)TOK * DH];
__device__ __half g_Wq[DH * DIN];      // [n][k]
__device__ __half g_Wk[DH * DIN];
__device__ __half g_Wv[DH * DIN];
__device__ __half g_Wo[DIN * DH];      // Wo^T [n=256][k=2048]

// ---------------- helpers ----------------
__device__ __forceinline__ uint32_t smem_u32(const void* p) {
    uint32_t a;
    asm("{ .reg .u64 t; cvta.to.shared.u64 t, %1; cvt.u32.u64 %0, t; }" : "=r"(a) : "l"(p));
    return a;
}
__device__ __forceinline__ void cpa16(uint32_t dst, const void* src) {
    asm volatile("cp.async.cg.shared.global [%0], [%1], 16;" :: "r"(dst), "l"(src));
}
#define CP_COMMIT() asm volatile("cp.async.commit_group;" ::: "memory")
#define CP_WAIT(n)  asm volatile("cp.async.wait_group %0;" :: "n"(n) : "memory")

#define LDSM4(r, a) asm volatile( \
    "ldmatrix.sync.aligned.m8n8.x4.shared.b16 {%0,%1,%2,%3}, [%4];" \
    : "=r"((r)[0]), "=r"((r)[1]), "=r"((r)[2]), "=r"((r)[3]) : "r"(a))

#define MMA16816(c, a, b0, b1) asm volatile( \
    "mma.sync.aligned.m16n8k16.row.col.f32.f16.f16.f32 " \
    "{%0,%1,%2,%3}, {%4,%5,%6,%7}, {%8,%9}, {%0,%1,%2,%3};" \
    : "+f"((c)[0]), "+f"((c)[1]), "+f"((c)[2]), "+f"((c)[3]) \
    : "r"((a)[0]), "r"((a)[1]), "r"((a)[2]), "r"((a)[3]), "r"(b0), "r"(b1))

__device__ __forceinline__ void split_h(float v, __half& h, __half& l) {
    h = __float2half_rn(v);
    l = __float2half_rn(v - __half2float(h));
}

// ============================================================================
// X split: x fp32 [TOK][256] -> g_Xhi/g_Xlo fp16
// ============================================================================
__global__ void xsplit(const float4* __restrict__ x) {
    size_t i = (size_t)blockIdx.x * blockDim.x + threadIdx.x;   // 1M threads, 4 elems
    float4 f = x[i];
    __half h0, l0, h1, l1, h2, l2, h3, l3;
    split_h(f.x, h0, l0); split_h(f.y, h1, l1);
    split_h(f.z, h2, l2); split_h(f.w, h3, l3);
    __half2* ph = reinterpret_cast<__half2*>(g_Xhi) + 2 * i;
    __half2* pl = reinterpret_cast<__half2*>(g_Xlo) + 2 * i;
    ph[0] = __half2(h0, h1); ph[1] = __half2(h2, h3);
    pl[0] = __half2(l0, l1); pl[1] = __half2(l2, l3);
}

// ============================================================================
// fused weight transpose:  all 4 matrices, W[K][N] -> out[N][K] fp16
// ============================================================================
__global__ void wconv_all(const float* __restrict__ Wq, const float* __restrict__ Wk,
                          const float* __restrict__ Wv, const float* __restrict__ Wo) {
    __shared__ float s[64][65];
    const int which = blockIdx.y;
    const float* W; __half* oh; int K, N;
    if (which == 0)      { W = Wq; oh = g_Wq; K = DIN; N = DH; }
    else if (which == 1) { W = Wk; oh = g_Wk; K = DIN; N = DH; }
    else if (which == 2) { W = Wv; oh = g_Wv; K = DIN; N = DH; }
    else                 { W = Wo; oh = g_Wo; K = DH;  N = DIN; }
    const int nt = N / 64;
    const int n0 = (blockIdx.x % nt) * 64, k0 = (blockIdx.x / nt) * 64;
    const int tx = threadIdx.x & 63, ty = threadIdx.x >> 6;
    for (int r = ty; r < 64; r += 4)
        s[r][tx] = W[(size_t)(k0 + r) * N + n0 + tx];
    __syncthreads();
    for (int r = ty; r < 64; r += 4)
        oh[(size_t)(n0 + r) * K + k0 + tx] = __float2half_rn(s[tx][r]);
}

// ============================================================================
// split-fp16 TN GEMM:  C[M][ldc] = (Ah+Al)[M][K] @ B[N][K]^T + bias
// CTA 128x128, 8 warps (2m x 4n), warp tile 64x32, BK=32.
// 3-stage cp.async pipeline, ONE sync per k-iter. 2 MMA terms: Ah*B + Al*B.
// smem/stage: Ah(10240) Al(10240) B(10240), pitch 80B  -> 30720B; x3 = 92160B
// ============================================================================
#define GSTAGE 30720
#define GSMEM  (3 * GSTAGE)

__global__ void __launch_bounds__(256, 2)
gemm_fp16(const __half* __restrict__ Ah, const __half* __restrict__ Al, int lda,
          const __half* __restrict__ B, int ldb,
          const float* __restrict__ bias, float* __restrict__ C, int ldc, int K)
{
    extern __shared__ char smem[];
    const uint32_t sbase = smem_u32(smem);
    const int tid = threadIdx.x, lane = tid & 31, wid = tid >> 5;
    const int wm = wid >> 2, wn = wid & 3;
    const size_t m0 = (size_t)blockIdx.x * 128;
    const size_t n0 = (size_t)blockIdx.y * 128;

    float acc[4][4][4];
    #pragma unroll
    for (int a = 0; a < 4; a++)
        #pragma unroll
        for (int b = 0; b < 4; b++)
            #pragma unroll
            for (int c = 0; c < 4; c++) acc[a][b][c] = 0.f;

    const int r = tid >> 1;          // 0..127
    const int cc0 = (tid & 1) * 2;   // 16B chunk 0/2

    const int KT = K / 32;

    #define LOAD_STAGE(s, kb) do { \
        uint32_t d = sbase + (s) * GSTAGE; \
        const __half* pah = Ah + (m0 + r) * (size_t)lda + (kb); \
        const __half* pal = Al + (m0 + r) * (size_t)lda + (kb); \
        const __half* pb  = B  + (n0 + r) * (size_t)ldb + (kb); \
        cpa16(d +         r * 80 + cc0 * 16,       pah + cc0 * 8); \
        cpa16(d +         r * 80 + (cc0 + 1) * 16, pah + (cc0 + 1) * 8); \
        cpa16(d + 10240 + r * 80 + cc0 * 16,       pal + cc0 * 8); \
        cpa16(d + 10240 + r * 80 + (cc0 + 1) * 16, pal + (cc0 + 1) * 8); \
        cpa16(d + 20480 + r * 80 + cc0 * 16,       pb + cc0 * 8); \
        cpa16(d + 20480 + r * 80 + (cc0 + 1) * 16, pb + (cc0 + 1) * 8); \
    } while (0)

    LOAD_STAGE(0, 0);
    CP_COMMIT();
    if (KT > 1) { LOAD_STAGE(1, 32); CP_COMMIT(); }

    int stage = 0;
    for (int kt = 0; kt < KT; kt++) {
        if (kt + 1 < KT) CP_WAIT(1); else CP_WAIT(0);
        __syncthreads();
        if (kt + 2 < KT) {
            int ns = stage + 2; if (ns >= 3) ns -= 3;
            LOAD_STAGE(ns, (kt + 2) * 32);
            CP_COMMIT();
        }

        const uint32_t s = sbase + stage * GSTAGE;
        const uint32_t arow = s +         (wm * 64 + (lane & 15)) * 80 + (lane >> 4) * 16;
        const uint32_t brow = s + 20480 + (wn * 32 + (lane & 15)) * 80 + (lane >> 4) * 16;

        #pragma unroll
        for (int kh = 0; kh < 2; kh++) {
            uint32_t bf[2][4];
            LDSM4(bf[0], brow + kh * 32);
            LDSM4(bf[1], brow + 1280 + kh * 32);
            #pragma unroll
            for (int mf = 0; mf < 4; mf++) {
                uint32_t ah[4], al[4];
                LDSM4(ah, arow + mf * 1280 + kh * 32);
                LDSM4(al, arow + 10240 + mf * 1280 + kh * 32);
                #pragma unroll
                for (int ng = 0; ng < 2; ng++) {
                    #pragma unroll
                    for (int nn = 0; nn < 2; nn++) {
                        float* c = acc[mf][ng * 2 + nn];
                        MMA16816(c, ah, bf[ng][nn], bf[ng][nn + 2]);
                        MMA16816(c, al, bf[ng][nn], bf[ng][nn + 2]);
                    }
                }
            }
        }
        stage++; if (stage >= 3) stage -= 3;
    }

    // epilogue: bias + store
    #pragma unroll
    for (int mf = 0; mf < 4; mf++) {
        const size_t row = m0 + wm * 64 + mf * 16 + (lane >> 2);
        #pragma unroll
        for (int nf = 0; nf < 4; nf++) {
            const size_t col = n0 + wn * 32 + nf * 8 + (lane & 3) * 2;
            const float b0 = __ldg(bias + col), b1 = __ldg(bias + col + 1);
            float2 v0 = { acc[mf][nf][0] + b0, acc[mf][nf][1] + b1 };
            float2 v1 = { acc[mf][nf][2] + b0, acc[mf][nf][3] + b1 };
            *reinterpret_cast<float2*>(C + row * (size_t)ldc + col)       = v0;
            *reinterpret_cast<float2*>(C + (row + 8) * (size_t)ldc + col) = v1;
        }
    }
}

// ============================================================================
// attention: per-token 8x8 head-vs-head softmax. 32 tokens/CTA.
// reads g_Q/g_K/g_V fp32, writes g_Ohi/g_Olo fp16
// ============================================================================
#define AP 33
#define ATT_SMEM ((256 * AP * 2 + 2048) * 4)

__global__ void __launch_bounds__(256, 2) attn_kernel() {
    extern __shared__ float sm[];
    float* sQ = sm;
    float* sK = sm + 256 * AP;
    float* sP = sm + 512 * AP;
    const int tid = threadIdx.x;
    const int g0 = blockIdx.x * 32;
    const int lt = tid >> 3, lh = tid & 7;

    float accL[HEADS];
    #pragma unroll
    for (int g = 0; g < HEADS; g++) accL[g] = 0.f;

    for (int dc = 0; dc < 8; dc++) {
        for (int i = tid; i < 8192; i += 256) {
            int t = i >> 8, c = i & 255;
            int j = (c >> 5) * DIN + dc * 32 + (c & 31);
            size_t src = (size_t)(g0 + t) * DH + j;
            sQ[c * AP + t] = g_Q[src];
            sK[c * AP + t] = g_K[src];
        }
        __syncthreads();
        #pragma unroll 4
        for (int d2 = 0; d2 < 32; d2++) {
            float qv = sQ[(lh * 32 + d2) * AP + lt];
            #pragma unroll
            for (int g = 0; g < HEADS; g++)
                accL[g] = fmaf(qv, sK[(g * 32 + d2) * AP + lt], accL[g]);
        }
        __syncthreads();
    }
    {
        const float scale = 0.0625f;
        float m = -3.4e38f;
        #pragma unroll
        for (int g = 0; g < HEADS; g++) { accL[g] *= scale; m = fmaxf(m, accL[g]); }
        float s = 0.f;
        #pragma unroll
        for (int g = 0; g < HEADS; g++) { accL[g] = __expf(accL[g] - m); s += accL[g]; }
        float inv = 1.f / s;
        #pragma unroll
        for (int g = 0; g < HEADS; g++)
            sP[(lt * HEADS + lh) * HEADS + g] = accL[g] * inv;
    }
    const int head = tid >> 5, dd = tid & 31;
    for (int dc = 0; dc < 8; dc++) {
        for (int i = tid; i < 8192; i += 256) {
            int t = i >> 8, c = i & 255;
            int j = (c >> 5) * DIN + dc * 32 + (c & 31);
            sK[c * AP + t] = g_V[(size_t)(g0 + t) * DH + j];
        }
        __syncthreads();   // also publishes sP on dc=0
        const int j = head * DIN + dc * 32 + dd;
        #pragma unroll 4
        for (int t = 0; t < 32; t++) {
            const float* pp = sP + (t * HEADS + head) * HEADS;
            float o = 0.f;
            #pragma unroll
            for (int g = 0; g < HEADS; g++)
                o = fmaf(pp[g], sK[(g * 32 + dd) * AP + t], o);
            __half h, l;
            split_h(o, h, l);
            size_t dst = (size_t)(g0 + t) * DH + j;
            g_Ohi[dst] = h;
            g_Olo[dst] = l;
        }
        __syncthreads();
    }
}

// ============================================================================
extern "C" void kernel_launch(void* const* d_in, const int* in_sizes, int n_in,
                              void* d_out, int out_size) {
    const float* x  = (const float*)d_in[0];
    const float* Wq = (const float*)d_in[1];
    const float* bq = (const float*)d_in[2];
    const float* Wk = (const float*)d_in[3];
    const float* bk = (const float*)d_in[4];
    const float* Wv = (const float*)d_in[5];
    const float* bv = (const float*)d_in[6];
    const float* Wo = (const float*)d_in[7];
    const float* bo = (const float*)d_in[8];
    float* out = (float*)d_out;

    cudaFuncSetAttribute(gemm_fp16,   cudaFuncAttributeMaxDynamicSharedMemorySize, GSMEM);
    cudaFuncSetAttribute(attn_kernel, cudaFuncAttributeMaxDynamicSharedMemorySize, ATT_SMEM);

    __half *Xhi, *Xlo, *Ohi, *Olo, *Wqd, *Wkd, *Wvd, *Wod;
    float *Qp, *Kp, *Vp;
    cudaGetSymbolAddress((void**)&Xhi, g_Xhi); cudaGetSymbolAddress((void**)&Xlo, g_Xlo);
    cudaGetSymbolAddress((void**)&Ohi, g_Ohi); cudaGetSymbolAddress((void**)&Olo, g_Olo);
    cudaGetSymbolAddress((void**)&Wqd, g_Wq);  cudaGetSymbolAddress((void**)&Wkd, g_Wk);
    cudaGetSymbolAddress((void**)&Wvd, g_Wv);  cudaGetSymbolAddress((void**)&Wod, g_Wo);
    cudaGetSymbolAddress((void**)&Qp, g_Q);
    cudaGetSymbolAddress((void**)&Kp, g_K);
    cudaGetSymbolAddress((void**)&Vp, g_V);

    // prep
    xsplit<<<4096, 256>>>((const float4*)x);
    wconv_all<<<dim3(128, 4), 256>>>(Wq, Wk, Wv, Wo);

    // QKV projections: M=16384, N=2048, K=256
    dim3 g1(TOK / 128, DH / 128);
    gemm_fp16<<<g1, 256, GSMEM>>>(Xhi, Xlo, DIN, Wqd, DIN, bq, Qp, DH, DIN);
    gemm_fp16<<<g1, 256, GSMEM>>>(Xhi, Xlo, DIN, Wkd, DIN, bk, Kp, DH, DIN);
    gemm_fp16<<<g1, 256, GSMEM>>>(Xhi, Xlo, DIN, Wvd, DIN, bv, Vp, DH, DIN);

    // attention
    attn_kernel<<<TOK / 32, 256, ATT_SMEM>>>();

    // out-proj: M=16384, N=256, K=2048
    dim3 g2(TOK / 128, DIN / 128);
    gemm_fp16<<<g2, 256, GSMEM>>>(Ohi, Olo, DH, Wod, DH, bo, out, DIN, DH);
}

// round 7
// speedup vs baseline: 3.1796x; 1.2907x over previous
#include <cuda_runtime.h>
#include <cuda_fp16.h>
#include <cstdint>

#define TOK   16384
#define DIN   256
#define DH    2048
#define HEADS 8

// ---------------- device scratch ----------------
__device__ __half g_Xh[(size_t)TOK * DIN];
__device__ __half g_Qh[(size_t)TOK * DH];
__device__ __half g_Kh[(size_t)TOK * DH];
__device__ __half g_Vh[(size_t)TOK * DH];
__device__ __half g_Oh[(size_t)TOK * DH];
__device__ __half g_Wq[DH * DIN];      // [n][k]
__device__ __half g_Wk[DH * DIN];
__device__ __half g_Wv[DH * DIN];
__device__ __half g_Wo[DIN * DH];      // Wo^T [n=256][k=2048]

// ---------------- helpers ----------------
__device__ __forceinline__ uint32_t smem_u32(const void* p) {
    uint32_t a;
    asm("{ .reg .u64 t; cvta.to.shared.u64 t, %1; cvt.u32.u64 %0, t; }" : "=r"(a) : "l"(p));
    return a;
}
__device__ __forceinline__ void cpa16(uint32_t dst, const void* src) {
    asm volatile("cp.async.cg.shared.global [%0], [%1], 16;" :: "r"(dst), "l"(src));
}
#define CP_COMMIT() asm volatile("cp.async.commit_group;" ::: "memory")
#define CP_WAIT(n)  asm volatile("cp.async.wait_group %0;" :: "n"(n) : "memory")

#define LDSM4(r, a) asm volatile( \
    "ldmatrix.sync.aligned.m8n8.x4.shared.b16 {%0,%1,%2,%3}, [%4];" \
    : "=r"((r)[0]), "=r"((r)[1]), "=r"((r)[2]), "=r"((r)[3]) : "r"(a))

#define MMA16816(c, a, b0, b1) asm volatile( \
    "mma.sync.aligned.m16n8k16.row.col.f32.f16.f16.f32 " \
    "{%0,%1,%2,%3}, {%4,%5,%6,%7}, {%8,%9}, {%0,%1,%2,%3};" \
    : "+f"((c)[0]), "+f"((c)[1]), "+f"((c)[2]), "+f"((c)[3]) \
    : "r"((a)[0]), "r"((a)[1]), "r"((a)[2]), "r"((a)[3]), "r"(b0), "r"(b1))

// ============================================================================
// X convert: fp32 -> fp16
// ============================================================================
__global__ void xconv(const float4* __restrict__ x) {
    size_t i = (size_t)blockIdx.x * blockDim.x + threadIdx.x;   // 1M threads, 4 elems
    float4 f = x[i];
    __half2* p = reinterpret_cast<__half2*>(g_Xh) + 2 * i;
    p[0] = __floats2half2_rn(f.x, f.y);
    p[1] = __floats2half2_rn(f.z, f.w);
}

// ============================================================================
// fused weight transpose: W[K][N] -> out[N][K] fp16
// ============================================================================
__global__ void wconv_all(const float* __restrict__ Wq, const float* __restrict__ Wk,
                          const float* __restrict__ Wv, const float* __restrict__ Wo) {
    __shared__ float s[64][65];
    const int which = blockIdx.y;
    const float* W; __half* oh; int K, N;
    if (which == 0)      { W = Wq; oh = g_Wq; K = DIN; N = DH; }
    else if (which == 1) { W = Wk; oh = g_Wk; K = DIN; N = DH; }
    else if (which == 2) { W = Wv; oh = g_Wv; K = DIN; N = DH; }
    else                 { W = Wo; oh = g_Wo; K = DH;  N = DIN; }
    const int nt = N / 64;
    const int n0 = (blockIdx.x % nt) * 64, k0 = (blockIdx.x / nt) * 64;
    const int tx = threadIdx.x & 63, ty = threadIdx.x >> 6;
    for (int r = ty; r < 64; r += 4)
        s[r][tx] = W[(size_t)(k0 + r) * N + n0 + tx];
    __syncthreads();
    for (int r = ty; r < 64; r += 4)
        oh[(size_t)(n0 + r) * K + k0 + tx] = __float2half_rn(s[tx][r]);
}

// ============================================================================
// fp16 TN GEMM: C[M][ldc] = A[M][K] @ B[N][K]^T + bias
// CTA 128x128, 4 warps (2m x 2n), warp tile 64x64, BK=32.
// 4-stage cp.async pipeline, one sync per k-iter, single fp16 MMA term.
// stage: A(10240) + B(10240) = 20480B, pitch 80B; 4 stages = 81920B
// ============================================================================
#define GST   20480
#define GSMEM (4 * GST)

template <bool HALF_OUT>
__global__ void __launch_bounds__(128, 2)
hgemm(const __half* __restrict__ A, int lda,
      const __half* __restrict__ B, int ldb,
      const float* __restrict__ bias, void* __restrict__ Cv, int ldc, int K)
{
    extern __shared__ char smem[];
    const uint32_t sbase = smem_u32(smem);
    const int tid = threadIdx.x, lane = tid & 31, wid = tid >> 5;
    const int wm = wid >> 1, wn = wid & 1;
    const size_t m0 = (size_t)blockIdx.x * 128;
    const size_t n0 = (size_t)blockIdx.y * 128;

    float acc[4][8][4];
    #pragma unroll
    for (int a = 0; a < 4; a++)
        #pragma unroll
        for (int b = 0; b < 8; b++)
            #pragma unroll
            for (int c = 0; c < 4; c++) acc[a][b][c] = 0.f;

    const int r = tid;   // 0..127: one A row + one B row per thread
    const int KT = K / 32;

    #define LOAD_STAGE(s, kb) do { \
        uint32_t d = sbase + (s) * GST; \
        const __half* pa = A + (m0 + r) * (size_t)lda + (kb); \
        const __half* pb = B + (n0 + r) * (size_t)ldb + (kb); \
        cpa16(d +         r * 80,      pa); \
        cpa16(d +         r * 80 + 16, pa + 8); \
        cpa16(d +         r * 80 + 32, pa + 16); \
        cpa16(d +         r * 80 + 48, pa + 24); \
        cpa16(d + 10240 + r * 80,      pb); \
        cpa16(d + 10240 + r * 80 + 16, pb + 8); \
        cpa16(d + 10240 + r * 80 + 32, pb + 16); \
        cpa16(d + 10240 + r * 80 + 48, pb + 24); \
    } while (0)

    LOAD_STAGE(0, 0); CP_COMMIT();
    if (KT > 1) { LOAD_STAGE(1, 32); CP_COMMIT(); }
    if (KT > 2) { LOAD_STAGE(2, 64); CP_COMMIT(); }

    for (int kt = 0; kt < KT; kt++) {
        if (kt + 1 >= KT)      CP_WAIT(0);
        else if (kt + 2 >= KT) CP_WAIT(1);
        else                   CP_WAIT(2);
        __syncthreads();
        if (kt + 3 < KT) { LOAD_STAGE((kt + 3) & 3, (kt + 3) * 32); CP_COMMIT(); }

        const uint32_t s = sbase + (kt & 3) * GST;
        const uint32_t arow = s +         (wm * 64 + (lane & 15)) * 80 + (lane >> 4) * 16;
        const uint32_t brow = s + 10240 + (wn * 64 + (lane & 15)) * 80 + (lane >> 4) * 16;

        #pragma unroll
        for (int kh = 0; kh < 2; kh++) {
            uint32_t bf[4][4];
            #pragma unroll
            for (int bq = 0; bq < 4; bq++)
                LDSM4(bf[bq], brow + bq * 1280 + kh * 32);
            #pragma unroll
            for (int mf = 0; mf < 4; mf++) {
                uint32_t ah[4];
                LDSM4(ah, arow + mf * 1280 + kh * 32);
                #pragma unroll
                for (int bq = 0; bq < 4; bq++) {
                    #pragma unroll
                    for (int nn = 0; nn < 2; nn++)
                        MMA16816(acc[mf][bq * 2 + nn], ah, bf[bq][nn], bf[bq][nn + 2]);
                }
            }
        }
    }

    // epilogue
    #pragma unroll
    for (int mf = 0; mf < 4; mf++) {
        const size_t row = m0 + wm * 64 + mf * 16 + (lane >> 2);
        #pragma unroll
        for (int no = 0; no < 8; no++) {
            const size_t col = n0 + wn * 64 + no * 8 + (lane & 3) * 2;
            const float b0 = __ldg(bias + col), b1 = __ldg(bias + col + 1);
            if (HALF_OUT) {
                __half* C = (__half*)Cv;
                *reinterpret_cast<__half2*>(C + row * (size_t)ldc + col) =
                    __floats2half2_rn(acc[mf][no][0] + b0, acc[mf][no][1] + b1);
                *reinterpret_cast<__half2*>(C + (row + 8) * (size_t)ldc + col) =
                    __floats2half2_rn(acc[mf][no][2] + b0, acc[mf][no][3] + b1);
            } else {
                float* C = (float*)Cv;
                float2 v0 = { acc[mf][no][0] + b0, acc[mf][no][1] + b1 };
                float2 v1 = { acc[mf][no][2] + b0, acc[mf][no][3] + b1 };
                *reinterpret_cast<float2*>(C + row * (size_t)ldc + col)       = v0;
                *reinterpret_cast<float2*>(C + (row + 8) * (size_t)ldc + col) = v1;
            }
        }
    }
}

// ============================================================================
// attention: per-token 8x8 head-vs-head softmax. 32 tokens/CTA.
// reads g_Qh/g_Kh/g_Vh fp16, writes g_Oh fp16
// ============================================================================
#define AP 33
#define ATT_SMEM ((256 * AP * 2 + 2048) * 4)

__global__ void __launch_bounds__(256, 2) attn_kernel() {
    extern __shared__ float sm[];
    float* sQ = sm;
    float* sK = sm + 256 * AP;
    float* sP = sm + 512 * AP;
    const int tid = threadIdx.x;
    const int g0 = blockIdx.x * 32;
    const int lt = tid >> 3, lh = tid & 7;

    float accL[HEADS];
    #pragma unroll
    for (int g = 0; g < HEADS; g++) accL[g] = 0.f;

    for (int dc = 0; dc < 8; dc++) {
        for (int i = tid; i < 4096; i += 256) {
            int t = i >> 7, c = (i & 127) * 2;
            int j = (c >> 5) * DIN + dc * 32 + (c & 31);
            size_t src = (size_t)(g0 + t) * DH + j;
            float2 qf = __half22float2(*reinterpret_cast<const __half2*>(g_Qh + src));
            float2 kf = __half22float2(*reinterpret_cast<const __half2*>(g_Kh + src));
            sQ[c * AP + t] = qf.x; sQ[(c + 1) * AP + t] = qf.y;
            sK[c * AP + t] = kf.x; sK[(c + 1) * AP + t] = kf.y;
        }
        __syncthreads();
        #pragma unroll 4
        for (int d2 = 0; d2 < 32; d2++) {
            float qv = sQ[(lh * 32 + d2) * AP + lt];
            #pragma unroll
            for (int g = 0; g < HEADS; g++)
                accL[g] = fmaf(qv, sK[(g * 32 + d2) * AP + lt], accL[g]);
        }
        __syncthreads();
    }
    {
        const float scale = 0.0625f;
        float m = -3.4e38f;
        #pragma unroll
        for (int g = 0; g < HEADS; g++) { accL[g] *= scale; m = fmaxf(m, accL[g]); }
        float s = 0.f;
        #pragma unroll
        for (int g = 0; g < HEADS; g++) { accL[g] = __expf(accL[g] - m); s += accL[g]; }
        float inv = 1.f / s;
        #pragma unroll
        for (int g = 0; g < HEADS; g++)
            sP[(lt * HEADS + lh) * HEADS + g] = accL[g] * inv;
    }
    const int head = tid >> 5, dd = tid & 31;
    for (int dc = 0; dc < 8; dc++) {
        for (int i = tid; i < 4096; i += 256) {
            int t = i >> 7, c = (i & 127) * 2;
            int j = (c >> 5) * DIN + dc * 32 + (c & 31);
            float2 vf = __half22float2(*reinterpret_cast<const __half2*>(g_Vh + (size_t)(g0 + t) * DH + j));
            sK[c * AP + t] = vf.x; sK[(c + 1) * AP + t] = vf.y;
        }
        __syncthreads();   // also publishes sP on dc=0
        const int j = head * DIN + dc * 32 + dd;
        #pragma unroll 4
        for (int t = 0; t < 32; t++) {
            const float* pp = sP + (t * HEADS + head) * HEADS;
            float o = 0.f;
            #pragma unroll
            for (int g = 0; g < HEADS; g++)
                o = fmaf(pp[g], sK[(g * 32 + dd) * AP + t], o);
            g_Oh[(size_t)(g0 + t) * DH + j] = __float2half_rn(o);
        }
        __syncthreads();
    }
}

// ============================================================================
extern "C" void kernel_launch(void* const* d_in, const int* in_sizes, int n_in,
                              void* d_out, int out_size) {
    const float* x  = (const float*)d_in[0];
    const float* Wq = (const float*)d_in[1];
    const float* bq = (const float*)d_in[2];
    const float* Wk = (const float*)d_in[3];
    const float* bk = (const float*)d_in[4];
    const float* Wv = (const float*)d_in[5];
    const float* bv = (const float*)d_in[6];
    const float* Wo = (const float*)d_in[7];
    const float* bo = (const float*)d_in[8];
    float* out = (float*)d_out;

    cudaFuncSetAttribute(hgemm<true>,  cudaFuncAttributeMaxDynamicSharedMemorySize, GSMEM);
    cudaFuncSetAttribute(hgemm<false>, cudaFuncAttributeMaxDynamicSharedMemorySize, GSMEM);
    cudaFuncSetAttribute(attn_kernel,  cudaFuncAttributeMaxDynamicSharedMemorySize, ATT_SMEM);

    __half *Xh, *Qh, *Kh, *Vh, *Oh, *Wqd, *Wkd, *Wvd, *Wod;
    cudaGetSymbolAddress((void**)&Xh, g_Xh);
    cudaGetSymbolAddress((void**)&Qh, g_Qh);
    cudaGetSymbolAddress((void**)&Kh, g_Kh);
    cudaGetSymbolAddress((void**)&Vh, g_Vh);
    cudaGetSymbolAddress((void**)&Oh, g_Oh);
    cudaGetSymbolAddress((void**)&Wqd, g_Wq); cudaGetSymbolAddress((void**)&Wkd, g_Wk);
    cudaGetSymbolAddress((void**)&Wvd, g_Wv); cudaGetSymbolAddress((void**)&Wod, g_Wo);

    // prep
    xconv<<<4096, 256>>>((const float4*)x);
    wconv_all<<<dim3(128, 4), 256>>>(Wq, Wk, Wv, Wo);

    // QKV projections: M=16384, N=2048, K=256
    dim3 g1(TOK / 128, DH / 128);
    hgemm<true><<<g1, 128, GSMEM>>>(Xh, DIN, Wqd, DIN, bq, Qh, DH, DIN);
    hgemm<true><<<g1, 128, GSMEM>>>(Xh, DIN, Wkd, DIN, bk, Kh, DH, DIN);
    hgemm<true><<<g1, 128, GSMEM>>>(Xh, DIN, Wvd, DIN, bv, Vh, DH, DIN);

    // attention
    attn_kernel<<<TOK / 32, 256, ATT_SMEM>>>();

    // out-proj: M=16384, N=256, K=2048
    dim3 g2(TOK / 128, DIN / 128);
    hgemm<false><<<g2, 128, GSMEM>>>(Oh, DH, Wod, DH, bo, out, DIN, DH);
}

// round 9
// speedup vs baseline: 3.6774x; 1.1566x over previous
#include <cuda_runtime.h>
#include <cuda_fp16.h>
#include <cstdint>

#define TOK   16384
#define DIN   256
#define DH    2048
#define HEADS 8

// ---------------- device scratch ----------------
__device__ __half g_Xh[(size_t)TOK * DIN];
__device__ __half g_Qh[(size_t)TOK * DH];
__device__ __half g_Kh[(size_t)TOK * DH];
__device__ __half g_Vh[(size_t)TOK * DH];
__device__ __half g_Oh[(size_t)TOK * DH];
__device__ __half g_Wq[DH * DIN];      // [n][k]
__device__ __half g_Wk[DH * DIN];
__device__ __half g_Wv[DH * DIN];
__device__ __half g_Wo[DIN * DH];      // Wo^T [n=256][k=2048]

// ---------------- helpers ----------------
__device__ __forceinline__ uint32_t smem_u32(const void* p) {
    uint32_t a;
    asm("{ .reg .u64 t; cvta.to.shared.u64 t, %1; cvt.u32.u64 %0, t; }" : "=r"(a) : "l"(p));
    return a;
}
__device__ __forceinline__ void cpa16(uint32_t dst, const void* src) {
    asm volatile("cp.async.cg.shared.global [%0], [%1], 16;" :: "r"(dst), "l"(src));
}
#define CP_COMMIT() asm volatile("cp.async.commit_group;" ::: "memory")
#define CP_WAIT(n)  asm volatile("cp.async.wait_group %0;" :: "n"(n) : "memory")

#define LDSM4(r, a) asm volatile( \
    "ldmatrix.sync.aligned.m8n8.x4.shared.b16 {%0,%1,%2,%3}, [%4];" \
    : "=r"((r)[0]), "=r"((r)[1]), "=r"((r)[2]), "=r"((r)[3]) : "r"(a))

#define MMA16816(c, a, b0, b1) asm volatile( \
    "mma.sync.aligned.m16n8k16.row.col.f32.f16.f16.f32 " \
    "{%0,%1,%2,%3}, {%4,%5,%6,%7}, {%8,%9}, {%0,%1,%2,%3};" \
    : "+f"((c)[0]), "+f"((c)[1]), "+f"((c)[2]), "+f"((c)[3]) \
    : "r"((a)[0]), "r"((a)[1]), "r"((a)[2]), "r"((a)[3]), "r"(b0), "r"(b1))

// ============================================================================
// X convert: fp32 -> fp16
// ============================================================================
__global__ void xconv(const float4* __restrict__ x) {
    size_t i = (size_t)blockIdx.x * blockDim.x + threadIdx.x;
    float4 f = x[i];
    __half2* p = reinterpret_cast<__half2*>(g_Xh) + 2 * i;
    p[0] = __floats2half2_rn(f.x, f.y);
    p[1] = __floats2half2_rn(f.z, f.w);
}

// ============================================================================
// fused weight transpose: W[K][N] -> out[N][K] fp16
// ============================================================================
__global__ void wconv_all(const float* __restrict__ Wq, const float* __restrict__ Wk,
                          const float* __restrict__ Wv, const float* __restrict__ Wo) {
    __shared__ float s[64][65];
    const int which = blockIdx.y;
    const float* W; __half* oh; int K, N;
    if (which == 0)      { W = Wq; oh = g_Wq; K = DIN; N = DH; }
    else if (which == 1) { W = Wk; oh = g_Wk; K = DIN; N = DH; }
    else if (which == 2) { W = Wv; oh = g_Wv; K = DIN; N = DH; }
    else                 { W = Wo; oh = g_Wo; K = DH;  N = DIN; }
    const int nt = N / 64;
    const int n0 = (blockIdx.x % nt) * 64, k0 = (blockIdx.x / nt) * 64;
    const int tx = threadIdx.x & 63, ty = threadIdx.x >> 6;
    for (int r = ty; r < 64; r += 4)
        s[r][tx] = W[(size_t)(k0 + r) * N + n0 + tx];
    __syncthreads();
    for (int r = ty; r < 64; r += 4)
        oh[(size_t)(n0 + r) * K + k0 + tx] = __float2half_rn(s[tx][r]);
}

// ============================================================================
// bias prefill for split-K output:  out[t][c] = bo[c]
// grid must cover TOK*DIN/4 float4s = 1048576 -> 4096 blocks x 256 threads
// ============================================================================
__global__ void biasfill(float* __restrict__ out, const float* __restrict__ bo) {
    __shared__ float4 sb[64];
    if (threadIdx.x < 64) sb[threadIdx.x] = ((const float4*)bo)[threadIdx.x];
    __syncthreads();
    size_t i = (size_t)blockIdx.x * blockDim.x + threadIdx.x;   // float4 index
    ((float4*)out)[i] = sb[i & 63];
}

// ============================================================================
// fp16 TN GEMM: C[M][ldc] = A[M][K_total] @ B[N][K_total]^T (+bias)
// CTA 128x128, 8 warps (2m x 4n), warp tile 64x32, BK=32.
// 4-stage cp.async pipeline, one sync per k-iter, single fp16 MMA term.
// stage: A(10240)+B(10240)=20480B pitch 80B; 4 stages = 81920B, 2 CTA/SM.
// MODE 0: half out + bias.  MODE 1: float out + bias.  MODE 2: float atomicAdd (bias prefilled).
// ============================================================================
#define GST   20480
#define GSMEM (4 * GST)

template <int MODE>
__global__ void __launch_bounds__(256, 2)
hgemm(const __half* __restrict__ A, int lda,
      const __half* __restrict__ B, int ldb,
      const float* __restrict__ bias, void* __restrict__ Cv, int ldc, int K)
{
    extern __shared__ char smem[];
    const uint32_t sbase = smem_u32(smem);
    const int tid = threadIdx.x, lane = tid & 31, wid = tid >> 5;
    const int wm = wid >> 2, wn = wid & 3;
    const size_t m0 = (size_t)blockIdx.x * 128;
    const size_t n0 = (size_t)blockIdx.y * 128;
    const size_t k0 = (size_t)blockIdx.z * K;     // split-K offset

    float acc[4][4][4];
    #pragma unroll
    for (int a = 0; a < 4; a++)
        #pragma unroll
        for (int b = 0; b < 4; b++)
            #pragma unroll
            for (int c = 0; c < 4; c++) acc[a][b][c] = 0.f;

    const int r = tid >> 1;          // 0..127
    const int cc0 = (tid & 1) * 2;   // 16B chunk 0/2
    const int KT = K / 32;

    #define LOAD_STAGE(s, kb) do { \
        uint32_t d = sbase + (s) * GST; \
        const __half* pa = A + (m0 + r) * (size_t)lda + k0 + (kb); \
        const __half* pb = B + (n0 + r) * (size_t)ldb + k0 + (kb); \
        cpa16(d +         r * 80 + cc0 * 16,       pa + cc0 * 8); \
        cpa16(d +         r * 80 + (cc0 + 1) * 16, pa + (cc0 + 1) * 8); \
        cpa16(d + 10240 + r * 80 + cc0 * 16,       pb + cc0 * 8); \
        cpa16(d + 10240 + r * 80 + (cc0 + 1) * 16, pb + (cc0 + 1) * 8); \
    } while (0)

    LOAD_STAGE(0, 0); CP_COMMIT();
    if (KT > 1) { LOAD_STAGE(1, 32); CP_COMMIT(); }
    if (KT > 2) { LOAD_STAGE(2, 64); CP_COMMIT(); }

    for (int kt = 0; kt < KT; kt++) {
        if (kt + 1 >= KT)      CP_WAIT(0);
        else if (kt + 2 >= KT) CP_WAIT(1);
        else                   CP_WAIT(2);
        __syncthreads();
        if (kt + 3 < KT) { LOAD_STAGE((kt + 3) & 3, (kt + 3) * 32); CP_COMMIT(); }

        const uint32_t s = sbase + (kt & 3) * GST;
        const uint32_t arow = s +         (wm * 64 + (lane & 15)) * 80 + (lane >> 4) * 16;
        const uint32_t brow = s + 10240 + (wn * 32 + (lane & 15)) * 80 + (lane >> 4) * 16;

        #pragma unroll
        for (int kh = 0; kh < 2; kh++) {
            uint32_t bf[2][4];
            LDSM4(bf[0], brow + kh * 32);
            LDSM4(bf[1], brow + 1280 + kh * 32);
            #pragma unroll
            for (int mf = 0; mf < 4; mf++) {
                uint32_t ah[4];
                LDSM4(ah, arow + mf * 1280 + kh * 32);
                #pragma unroll
                for (int ng = 0; ng < 2; ng++) {
                    #pragma unroll
                    for (int nn = 0; nn < 2; nn++)
                        MMA16816(acc[mf][ng * 2 + nn], ah, bf[ng][nn], bf[ng][nn + 2]);
                }
            }
        }
    }

    // epilogue
    #pragma unroll
    for (int mf = 0; mf < 4; mf++) {
        const size_t row = m0 + wm * 64 + mf * 16 + (lane >> 2);
        #pragma unroll
        for (int nf = 0; nf < 4; nf++) {
            const size_t col = n0 + wn * 32 + nf * 8 + (lane & 3) * 2;
            if (MODE == 0) {
                const float b0 = __ldg(bias + col), b1 = __ldg(bias + col + 1);
                __half* C = (__half*)Cv;
                *reinterpret_cast<__half2*>(C + row * (size_t)ldc + col) =
                    __floats2half2_rn(acc[mf][nf][0] + b0, acc[mf][nf][1] + b1);
                *reinterpret_cast<__half2*>(C + (row + 8) * (size_t)ldc + col) =
                    __floats2half2_rn(acc[mf][nf][2] + b0, acc[mf][nf][3] + b1);
            } else if (MODE == 1) {
                const float b0 = __ldg(bias + col), b1 = __ldg(bias + col + 1);
                float* C = (float*)Cv;
                float2 v0 = { acc[mf][nf][0] + b0, acc[mf][nf][1] + b1 };
                float2 v1 = { acc[mf][nf][2] + b0, acc[mf][nf][3] + b1 };
                *reinterpret_cast<float2*>(C + row * (size_t)ldc + col)       = v0;
                *reinterpret_cast<float2*>(C + (row + 8) * (size_t)ldc + col) = v1;
            } else {
                float* C = (float*)Cv;
                atomicAdd(C + row * (size_t)ldc + col,           acc[mf][nf][0]);
                atomicAdd(C + row * (size_t)ldc + col + 1,       acc[mf][nf][1]);
                atomicAdd(C + (row + 8) * (size_t)ldc + col,     acc[mf][nf][2]);
                atomicAdd(C + (row + 8) * (size_t)ldc + col + 1, acc[mf][nf][3]);
            }
        }
    }
}

// ============================================================================
// attention: per-token 8x8 head-vs-head softmax. 32 tokens/CTA.
// ============================================================================
#define AP 33
#define ATT_SMEM ((256 * AP * 2 + 2048) * 4)

__global__ void __launch_bounds__(256, 2) attn_kernel() {
    extern __shared__ float sm[];
    float* sQ = sm;
    float* sK = sm + 256 * AP;
    float* sP = sm + 512 * AP;
    const int tid = threadIdx.x;
    const int g0 = blockIdx.x * 32;
    const int lt = tid >> 3, lh = tid & 7;

    float accL[HEADS];
    #pragma unroll
    for (int g = 0; g < HEADS; g++) accL[g] = 0.f;

    for (int dc = 0; dc < 8; dc++) {
        for (int i = tid; i < 4096; i += 256) {
            int t = i >> 7, c = (i & 127) * 2;
            int j = (c >> 5) * DIN + dc * 32 + (c & 31);
            size_t src = (size_t)(g0 + t) * DH + j;
            float2 qf = __half22float2(*reinterpret_cast<const __half2*>(g_Qh + src));
            float2 kf = __half22float2(*reinterpret_cast<const __half2*>(g_Kh + src));
            sQ[c * AP + t] = qf.x; sQ[(c + 1) * AP + t] = qf.y;
            sK[c * AP + t] = kf.x; sK[(c + 1) * AP + t] = kf.y;
        }
        __syncthreads();
        #pragma unroll 4
        for (int d2 = 0; d2 < 32; d2++) {
            float qv = sQ[(lh * 32 + d2) * AP + lt];
            #pragma unroll
            for (int g = 0; g < HEADS; g++)
                accL[g] = fmaf(qv, sK[(g * 32 + d2) * AP + lt], accL[g]);
        }
        __syncthreads();
    }
    {
        const float scale = 0.0625f;
        float m = -3.4e38f;
        #pragma unroll
        for (int g = 0; g < HEADS; g++) { accL[g] *= scale; m = fmaxf(m, accL[g]); }
        float s = 0.f;
        #pragma unroll
        for (int g = 0; g < HEADS; g++) { accL[g] = __expf(accL[g] - m); s += accL[g]; }
        float inv = 1.f / s;
        #pragma unroll
        for (int g = 0; g < HEADS; g++)
            sP[(lt * HEADS + lh) * HEADS + g] = accL[g] * inv;
    }
    const int head = tid >> 5, dd = tid & 31;
    for (int dc = 0; dc < 8; dc++) {
        for (int i = tid; i < 4096; i += 256) {
            int t = i >> 7, c = (i & 127) * 2;
            int j = (c >> 5) * DIN + dc * 32 + (c & 31);
            float2 vf = __half22float2(*reinterpret_cast<const __half2*>(g_Vh + (size_t)(g0 + t) * DH + j));
            sK[c * AP + t] = vf.x; sK[(c + 1) * AP + t] = vf.y;
        }
        __syncthreads();
        const int j = head * DIN + dc * 32 + dd;
        #pragma unroll 4
        for (int t = 0; t < 32; t++) {
            const float* pp = sP + (t * HEADS + head) * HEADS;
            float o = 0.f;
            #pragma unroll
            for (int g = 0; g < HEADS; g++)
                o = fmaf(pp[g], sK[(g * 32 + dd) * AP + t], o);
            g_Oh[(size_t)(g0 + t) * DH + j] = __float2half_rn(o);
        }
        __syncthreads();
    }
}

// ============================================================================
extern "C" void kernel_launch(void* const* d_in, const int* in_sizes, int n_in,
                              void* d_out, int out_size) {
    const float* x  = (const float*)d_in[0];
    const float* Wq = (const float*)d_in[1];
    const float* bq = (const float*)d_in[2];
    const float* Wk = (const float*)d_in[3];
    const float* bk = (const float*)d_in[4];
    const float* Wv = (const float*)d_in[5];
    const float* bv = (const float*)d_in[6];
    const float* Wo = (const float*)d_in[7];
    const float* bo = (const float*)d_in[8];
    float* out = (float*)d_out;

    cudaFuncSetAttribute(hgemm<0>, cudaFuncAttributeMaxDynamicSharedMemorySize, GSMEM);
    cudaFuncSetAttribute(hgemm<2>, cudaFuncAttributeMaxDynamicSharedMemorySize, GSMEM);
    cudaFuncSetAttribute(attn_kernel, cudaFuncAttributeMaxDynamicSharedMemorySize, ATT_SMEM);

    __half *Xh, *Qh, *Kh, *Vh, *Oh, *Wqd, *Wkd, *Wvd, *Wod;
    cudaGetSymbolAddress((void**)&Xh, g_Xh);
    cudaGetSymbolAddress((void**)&Qh, g_Qh);
    cudaGetSymbolAddress((void**)&Kh, g_Kh);
    cudaGetSymbolAddress((void**)&Vh, g_Vh);
    cudaGetSymbolAddress((void**)&Oh, g_Oh);
    cudaGetSymbolAddress((void**)&Wqd, g_Wq); cudaGetSymbolAddress((void**)&Wkd, g_Wk);
    cudaGetSymbolAddress((void**)&Wvd, g_Wv); cudaGetSymbolAddress((void**)&Wod, g_Wo);

    // prep
    xconv<<<4096, 256>>>((const float4*)x);
    wconv_all<<<dim3(128, 4), 256>>>(Wq, Wk, Wv, Wo);

    // QKV projections: M=16384, N=2048, K=256
    dim3 g1(TOK / 128, DH / 128, 1);
    hgemm<0><<<g1, 256, GSMEM>>>(Xh, DIN, Wqd, DIN, bq, Qh, DH, DIN);
    hgemm<0><<<g1, 256, GSMEM>>>(Xh, DIN, Wkd, DIN, bk, Kh, DH, DIN);
    hgemm<0><<<g1, 256, GSMEM>>>(Xh, DIN, Wvd, DIN, bv, Vh, DH, DIN);

    // attention
    attn_kernel<<<TOK / 32, 256, ATT_SMEM>>>();

    // out-proj: M=16384, N=256, K=2048 split-K x2, atomic accumulate onto bias
    biasfill<<<(TOK * DIN / 4) / 256, 256>>>(out, bo);   // 4096 blocks: exactly out_size
    dim3 g2(TOK / 128, DIN / 128, 2);
    hgemm<2><<<g2, 256, GSMEM>>>(Oh, DH, Wod, DH, nullptr, out, DIN, DH / 2);
}